// round 5
// baseline (speedup 1.0000x reference)
#include <cuda_runtime.h>
#include <cuda_bf16.h>
#include <cstdint>

// ============================================================================
// Problem constants
// ============================================================================
#define HEAD_DIM   128
#define NUM_HEADS  2
#define KWIN       32
#define KD         4096            // KWIN * HEAD_DIM
#define RESCALE    0.015625f       // (32*128)^-0.5

#define MT      64                 // M tile rows ((w,h) pairs) -> 32 windows
#define WTILE   32                 // windows per block
#define NT      32                 // gate outputs per head
#define KCHUNK  128                // K chunk = one full token-head row
#define NITER   (KD / KCHUNK)      // 32
#define NSTAGE  4                  // smem pipeline depth

#define NCOPY   192                // copy blocks appended to the fused grid
#define MAXROWS 65536              // compressed rows upper bound (actual 40000)

// ============================================================================
// Scratch (__device__ globals; allocation-free rule)
// ============================================================================
__device__ __nv_bfloat16 g_gw[NT * KD];            // 256 KB bf16 gate weight
__device__ uint32_t      g_bm[MAXROWS / 32];       // dest-row bitmap

// ============================================================================
// Helpers
// ============================================================================
__device__ __forceinline__ uint32_t smem_u32(const void* p) {
    uint32_t a;
    asm("{ .reg .u64 t; cvta.to.shared.u64 t, %1; cvt.u32.u64 %0, t; }"
        : "=r"(a) : "l"(p));
    return a;
}

__device__ __forceinline__ void sts64(uint32_t addr, uint2 v) {
    asm volatile("st.shared.v2.b32 [%0], {%1, %2};"
                 :: "r"(addr), "r"(v.x), "r"(v.y) : "memory");
}

__device__ __forceinline__ void sts128(uint32_t addr, uint4 v) {
    asm volatile("st.shared.v4.b32 [%0], {%1, %2, %3, %4};"
                 :: "r"(addr), "r"(v.x), "r"(v.y), "r"(v.z), "r"(v.w) : "memory");
}

__device__ __forceinline__ uint2 pack_bf16x4(float4 f) {
    __nv_bfloat162 lo = __floats2bfloat162_rn(f.x, f.y);
    __nv_bfloat162 hi = __floats2bfloat162_rn(f.z, f.w);
    uint2 r;
    r.x = *reinterpret_cast<uint32_t*>(&lo);
    r.y = *reinterpret_cast<uint32_t*>(&hi);
    return r;
}

__device__ __forceinline__ void ldmatrix_x4(uint32_t* r, uint32_t addr) {
    asm volatile("ldmatrix.sync.aligned.m8n8.x4.shared.b16 {%0,%1,%2,%3}, [%4];"
                 : "=r"(r[0]), "=r"(r[1]), "=r"(r[2]), "=r"(r[3])
                 : "r"(addr));
}

__device__ __forceinline__ void mma_bf16(float* d, const uint32_t* a,
                                         uint32_t b0, uint32_t b1) {
    asm volatile(
        "mma.sync.aligned.m16n8k16.row.col.f32.bf16.bf16.f32 "
        "{%0,%1,%2,%3}, {%4,%5,%6,%7}, {%8,%9}, {%0,%1,%2,%3};"
        : "+f"(d[0]), "+f"(d[1]), "+f"(d[2]), "+f"(d[3])
        : "r"(a[0]), "r"(a[1]), "r"(a[2]), "r"(a[3]), "r"(b0), "r"(b1));
}

__device__ __forceinline__ float sigf(float x) {
    return 1.0f / (1.0f + __expf(-x * RESCALE));
}

// named producer/consumer barriers: full[b] = 1+b, empty[b] = 5+b
#define BAR_ARRIVE(id) asm volatile("bar.arrive %0, 256;" :: "r"(id) : "memory")
#define BAR_SYNC(id)   asm volatile("bar.sync %0, 256;"   :: "r"(id) : "memory")

// ============================================================================
// Pre-kernels
// ============================================================================
__global__ void cvt_gw_kernel(const float* __restrict__ gw) {
    int i = blockIdx.x * blockDim.x + threadIdx.x;     // 32768 float4 tasks
    float4 v = reinterpret_cast<const float4*>(gw)[i];
    reinterpret_cast<uint2*>(g_gw)[i] = pack_bf16x4(v);
}

__global__ void zero_bm_kernel(int nwords) {
    int i = blockIdx.x * blockDim.x + threadIdx.x;
    if (i < nwords) g_bm[i] = 0u;
}

__global__ void set_bm_kernel(const int* __restrict__ dest, int W) {
    int i = blockIdx.x * blockDim.x + threadIdx.x;
    if (i < W) {
        int d = dest[i];
        atomicOr(&g_bm[d >> 5], 1u << (d & 31));
    }
}

// ============================================================================
// Fused kernel.
//   Blocks [0, nblk): warp-specialized GEMM.
//     warps 0-3 consumers: ldmatrix + MMA over 4-stage smem pipeline.
//     warps 4-7 producers: gather fp32 -> bf16 -> STS, up to 4 stages ahead.
//   Blocks [nblk, nblk+NCOPY): bitmap-masked copy of cbuf -> out.
// ============================================================================
struct SmemT {
    __align__(256) __nv_bfloat16 A[NSTAGE][MT * KCHUNK];  // 4 x 16 KB
    __align__(256) __nv_bfloat16 B[NSTAGE][NT * KCHUNK];  // 4 x  8 KB
    int   widx[WTILE * KWIN];                             //  4 KB
    float g[MT * NT];                                     //  8 KB
    int   dst[WTILE];
};
#define SMEM_BYTES ((int)sizeof(SmemT))

__global__ __launch_bounds__(256, 2)
void fused_kernel(const float* __restrict__ buffer,
                  const float* __restrict__ cbuf,
                  const int*   __restrict__ widx,
                  const int*   __restrict__ dest,
                  float*       __restrict__ out,
                  int W, int Mtot, int nblk, int crows)
{
    extern __shared__ char smraw[];
    SmemT& sm = *reinterpret_cast<SmemT*>(smraw);

    const int tid = threadIdx.x;

    // ---------------- copy blocks ----------------
    if (blockIdx.x >= nblk) {
        int cb  = blockIdx.x - nblk;
        int rpb = (crows + NCOPY - 1) / NCOPY;
        int r0  = cb * rpb;
        int r1  = min(r0 + rpb, crows);
        const float4* src4 = reinterpret_cast<const float4*>(cbuf);
        float4*       dst4 = reinterpret_cast<float4*>(out);
        int rsub = tid >> 6;
        int lane = tid & 63;
        for (int r = r0 + rsub; r < r1; r += 4) {
            if ((g_bm[r >> 5] >> (r & 31)) & 1u) continue;   // dest row: skip
            dst4[(size_t)r * 64 + lane] = src4[(size_t)r * 64 + lane];
        }
        return;
    }

    // ---------------- GEMM blocks ----------------
    const int warp = tid >> 5;
    const int lid  = tid & 31;

    const int m_base = blockIdx.x * MT;
    const int w_base = blockIdx.x * WTILE;

    // stage window indices + dest slots (padded windows -> slot 0, finite data)
    #pragma unroll
    for (int rep = 0; rep < 4; rep++) {
        int t  = rep * 256 + tid;                      // 1024 entries
        int wl = t >> 5;
        int wg = w_base + wl;
        sm.widx[t] = (wg < W) ? widx[(size_t)wg * KWIN + (t & 31)] : 0;
    }
    if (tid < WTILE) {
        int wg = w_base + tid;
        sm.dst[tid] = (wg < W) ? dest[wg] : 0;
    }
    __syncthreads();

    if (warp >= 4) {
        // ================= PRODUCERS (warps 4-7, 128 threads) =================
        const int ptid = tid & 127;
        for (int it = 0; it < NITER; it++) {
            int b = it & (NSTAGE - 1);
            if (it >= NSTAGE) BAR_SYNC(5 + b);         // wait stage empty

            uint32_t A_base = smem_u32(sm.A[b]);
            uint32_t B_base = smem_u32(sm.B[b]);

            // A: 2048 float4 tasks / 128 threads = 16 each; 2 batches of 8
            #pragma unroll
            for (int batch = 0; batch < 2; batch++) {
                float4 ra[8];
                #pragma unroll
                for (int r8 = 0; r8 < 8; r8++) {
                    int task = (batch * 8 + r8) * 128 + ptid;
                    int row  = task >> 5;
                    int c4   = task & 31;
                    int slot = sm.widx[(row >> 1) * KWIN + it];
                    ra[r8] = *reinterpret_cast<const float4*>(
                        buffer + ((size_t)slot * (NUM_HEADS * HEAD_DIM)
                                  + (row & 1) * HEAD_DIM + c4 * 4));
                }
                #pragma unroll
                for (int r8 = 0; r8 < 8; r8++) {
                    int task = (batch * 8 + r8) * 128 + ptid;
                    int row  = task >> 5;
                    int c4   = task & 31;
                    uint32_t ch = ((uint32_t)(c4 >> 1)) ^ (uint32_t)(row & 7);
                    sts64(A_base + row * 256 + ch * 16 + (c4 & 1) * 8,
                          pack_bf16x4(ra[r8]));
                }
            }

            // B: 512 uint4 tasks / 128 threads = 4 each
            uint4 rb[4];
            #pragma unroll
            for (int r4 = 0; r4 < 4; r4++) {
                int task = r4 * 128 + ptid;
                int row  = task >> 4;                  // 0..31
                int c16  = task & 15;
                rb[r4] = *reinterpret_cast<const uint4*>(
                    g_gw + (size_t)row * KD + it * KCHUNK + c16 * 8);
            }
            #pragma unroll
            for (int r4 = 0; r4 < 4; r4++) {
                int task = r4 * 128 + ptid;
                int row  = task >> 4;
                int c16  = task & 15;
                uint32_t ch = ((uint32_t)c16) ^ (uint32_t)(row & 7);
                sts128(B_base + row * 256 + ch * 16, rb[r4]);
            }

            BAR_ARRIVE(1 + b);                         // stage full
        }
    } else {
        // ================= CONSUMERS (warps 0-3) =================
        const int wm = warp * 16;                      // M rows wm..wm+15
        const int g  = lid >> 3;
        const int r  = lid & 7;

        const int rowA = wm + ((g & 1) << 3) + r;
        const int cA   = g >> 1;
        const uint32_t xA = (uint32_t)(rowA & 7);
        const int nB0  = ((g >> 1) << 3) + r;          // n 0..15 half
        const int cB   = g & 1;
        const uint32_t xB = (uint32_t)r;               // nB&7 == r for both halves

        float acc[4][4] = {};                          // 4 n8 tiles x 4

        for (int it = 0; it < NITER; it++) {
            int b = it & (NSTAGE - 1);
            BAR_SYNC(1 + b);                           // wait stage full

            uint32_t baseA  = smem_u32(sm.A[b]) + rowA * 256;
            uint32_t baseB0 = smem_u32(sm.B[b]) + nB0 * 256;
            uint32_t baseB1 = baseB0 + 16 * 256;

            #pragma unroll
            for (int ks = 0; ks < 8; ks++) {
                uint32_t a[4], b0[4], b1[4];
                uint32_t chA = ((uint32_t)(ks * 2 + cA)) ^ xA;
                uint32_t chB = ((uint32_t)(ks * 2 + cB)) ^ xB;
                ldmatrix_x4(a,  baseA  + chA * 16);
                ldmatrix_x4(b0, baseB0 + chB * 16);
                ldmatrix_x4(b1, baseB1 + chB * 16);
                mma_bf16(acc[0], a, b0[0], b0[1]);
                mma_bf16(acc[1], a, b0[2], b0[3]);
                mma_bf16(acc[2], a, b1[0], b1[1]);
                mma_bf16(acc[3], a, b1[2], b1[3]);
            }

            BAR_ARRIVE(5 + b);                         // stage empty
        }

        // gates: sigmoid -> smem (rows wm..wm+15, all 32 n)
        int row0 = wm + (lid >> 2);
        int row1 = row0 + 8;
        #pragma unroll
        for (int j = 0; j < 4; j++) {
            int n0 = j * 8 + (lid & 3) * 2;
            sm.g[row0 * NT + n0]     = sigf(acc[j][0]);
            sm.g[row0 * NT + n0 + 1] = sigf(acc[j][1]);
            sm.g[row1 * NT + n0]     = sigf(acc[j][2]);
            sm.g[row1 * NT + n0 + 1] = sigf(acc[j][3]);
        }
    }

    __syncthreads();

    // ---- gated reduction + scatter (all 256 threads; tokens L2-hot) ----
    const int wsub = tid >> 6;
    const int h    = (tid >> 5) & 1;
    const int dq   = tid & 31;

    for (int p = 0; p < 8; p++) {
        int wl = p * 4 + wsub;
        int wg = w_base + wl;
        if (wg >= W) continue;
        const float* gp = sm.g + (wl * 2 + h) * NT;
        const int*   sp = sm.widx + wl * KWIN;
        float4 acc4 = make_float4(0.f, 0.f, 0.f, 0.f);
        #pragma unroll 8
        for (int k = 0; k < KWIN; k++) {
            float gk = gp[k];
            const float4 t4 = *reinterpret_cast<const float4*>(
                buffer + ((size_t)sp[k] * (NUM_HEADS * HEAD_DIM)
                          + h * HEAD_DIM + dq * 4));
            acc4.x += gk * t4.x;
            acc4.y += gk * t4.y;
            acc4.z += gk * t4.z;
            acc4.w += gk * t4.w;
        }
        *reinterpret_cast<float4*>(
            out + ((size_t)sm.dst[wl] * (NUM_HEADS * HEAD_DIM)
                   + h * HEAD_DIM + dq * 4)) = acc4;
    }
}

// ============================================================================
// Launch
// ============================================================================
extern "C" void kernel_launch(void* const* d_in, const int* in_sizes, int n_in,
                              void* d_out, int out_size)
{
    const float* buffer = (const float*)d_in[0];
    const float* cbuf   = (const float*)d_in[1];
    const float* gw     = (const float*)d_in[2];
    const int*   widx   = (const int*)d_in[3];
    const int*   dest   = (const int*)d_in[4];
    int W     = in_sizes[4];
    int crows = out_size / (NUM_HEADS * HEAD_DIM);

    cudaFuncSetAttribute(fused_kernel,
                         cudaFuncAttributeMaxDynamicSharedMemorySize, SMEM_BYTES);

    // gate_weight -> bf16 scratch
    cvt_gw_kernel<<<128, 256>>>(gw);
    // dest bitmap
    int nwords = (crows + 31) / 32;
    zero_bm_kernel<<<(nwords + 255) / 256, 256>>>(nwords);
    if (W > 0) set_bm_kernel<<<(W + 255) / 256, 256>>>(dest, W);

    int Mtot = 2 * W;
    int nblk = (Mtot + MT - 1) / MT;          // GEMM blocks (0 allowed)
    fused_kernel<<<nblk + NCOPY, 256, SMEM_BYTES>>>(
        buffer, cbuf, widx, dest, (float*)d_out, W, Mtot, nblk, crows);
}

// round 6
// speedup vs baseline: 1.3328x; 1.3328x over previous
#include <cuda_runtime.h>
#include <cuda_bf16.h>
#include <cstdint>

// ============================================================================
// Problem constants
// ============================================================================
#define HEAD_DIM   128
#define NUM_HEADS  2
#define KWIN       32
#define KD         4096            // KWIN * HEAD_DIM
#define RESCALE    0.015625f       // (32*128)^-0.5

#define MT      64                 // M tile rows ((w,h) pairs) -> 32 windows
#define WTILE   32                 // windows per block
#define NT      32                 // gate outputs per head
#define KC      64                 // K chunk (fp32 elements) = half token row
#define NITER   (KD / KC)          // 64
#define NSTAGE  4                  // cp.async pipeline depth

#define NCOPY   192
#define MAXROWS 65536

// ============================================================================
// Scratch (__device__ globals; allocation-free rule)
// ============================================================================
__device__ __nv_bfloat16 g_gw[NT * KD];            // 256 KB bf16 gate weight
__device__ uint32_t      g_bm[MAXROWS / 32];       // dest-row bitmap

// ============================================================================
// Helpers
// ============================================================================
__device__ __forceinline__ uint32_t smem_u32(const void* p) {
    uint32_t a;
    asm("{ .reg .u64 t; cvta.to.shared.u64 t, %1; cvt.u32.u64 %0, t; }"
        : "=r"(a) : "l"(p));
    return a;
}

__device__ __forceinline__ void cp16(uint32_t dst, const void* src) {
    asm volatile("cp.async.cg.shared.global [%0], [%1], 16;"
                 :: "r"(dst), "l"(src) : "memory");
}
#define CP_COMMIT() asm volatile("cp.async.commit_group;" ::: "memory")
#define CP_WAIT()   asm volatile("cp.async.wait_group %0;" :: "n"(NSTAGE - 2) : "memory")

__device__ __forceinline__ float2 lds64(uint32_t a) {
    float2 v;
    asm volatile("ld.shared.v2.f32 {%0,%1}, [%2];"
                 : "=f"(v.x), "=f"(v.y) : "r"(a));
    return v;
}

__device__ __forceinline__ uint32_t pack2(float2 f) {
    __nv_bfloat162 h = __floats2bfloat162_rn(f.x, f.y);
    return *reinterpret_cast<uint32_t*>(&h);
}

__device__ __forceinline__ uint2 pack_bf16x4(float4 f) {
    __nv_bfloat162 lo = __floats2bfloat162_rn(f.x, f.y);
    __nv_bfloat162 hi = __floats2bfloat162_rn(f.z, f.w);
    uint2 r;
    r.x = *reinterpret_cast<uint32_t*>(&lo);
    r.y = *reinterpret_cast<uint32_t*>(&hi);
    return r;
}

__device__ __forceinline__ void ldmatrix_x4(uint32_t* r, uint32_t addr) {
    asm volatile("ldmatrix.sync.aligned.m8n8.x4.shared.b16 {%0,%1,%2,%3}, [%4];"
                 : "=r"(r[0]), "=r"(r[1]), "=r"(r[2]), "=r"(r[3])
                 : "r"(addr));
}

__device__ __forceinline__ void mma_bf16(float* d, const uint32_t* a,
                                         uint32_t b0, uint32_t b1) {
    asm volatile(
        "mma.sync.aligned.m16n8k16.row.col.f32.bf16.bf16.f32 "
        "{%0,%1,%2,%3}, {%4,%5,%6,%7}, {%8,%9}, {%0,%1,%2,%3};"
        : "+f"(d[0]), "+f"(d[1]), "+f"(d[2]), "+f"(d[3])
        : "r"(a[0]), "r"(a[1]), "r"(a[2]), "r"(a[3]), "r"(b0), "r"(b1));
}

__device__ __forceinline__ float sigf(float x) {
    return 1.0f / (1.0f + __expf(-x * RESCALE));
}

// ============================================================================
// Pre-kernels
// ============================================================================
__global__ void cvt_gw_kernel(const float* __restrict__ gw) {
    int i = blockIdx.x * blockDim.x + threadIdx.x;     // 32768 float4 tasks
    float4 v = reinterpret_cast<const float4*>(gw)[i];
    reinterpret_cast<uint2*>(g_gw)[i] = pack_bf16x4(v);
}

__global__ void zero_bm_kernel(int nwords) {
    int i = blockIdx.x * blockDim.x + threadIdx.x;
    if (i < nwords) g_bm[i] = 0u;
}

__global__ void set_bm_kernel(const int* __restrict__ dest, int W) {
    int i = blockIdx.x * blockDim.x + threadIdx.x;
    if (i < W) {
        int d = dest[i];
        atomicOr(&g_bm[d >> 5], 1u << (d & 31));
    }
}

// ============================================================================
// Fused kernel.
//   Blocks [0, nblk): gather GEMM via 4-stage cp.async pipeline.
//     A: fp32 in smem (swizzled 8B granules), converted to bf16 at consume.
//     B: bf16 in smem (from g_gw), ldmatrix.
//   Blocks [nblk, nblk+NCOPY): bitmap-masked copy of cbuf -> out.
// ============================================================================
struct SmemT {
    __align__(256) float          A[NSTAGE][MT * KC];   // 4 x 16 KB fp32
    __align__(256) __nv_bfloat16  B[NSTAGE][NT * KC];   // 4 x  4 KB bf16
    int   widx[WTILE * KWIN];                           //  4 KB
    float g[MT * NT];                                   //  8 KB
    int   dst[WTILE];
};
#define SMEM_BYTES ((int)sizeof(SmemT))

__global__ __launch_bounds__(256, 2)
void fused_kernel(const float* __restrict__ buffer,
                  const float* __restrict__ cbuf,
                  const int*   __restrict__ widx,
                  const int*   __restrict__ dest,
                  float*       __restrict__ out,
                  int W, int Mtot, int nblk, int crows)
{
    extern __shared__ char smraw[];
    SmemT& sm = *reinterpret_cast<SmemT*>(smraw);

    const int tid = threadIdx.x;

    // ---------------- copy blocks ----------------
    if (blockIdx.x >= nblk) {
        int cb  = blockIdx.x - nblk;
        int rpb = (crows + NCOPY - 1) / NCOPY;
        int r0  = cb * rpb;
        int r1  = min(r0 + rpb, crows);
        const float4* src4 = reinterpret_cast<const float4*>(cbuf);
        float4*       dst4 = reinterpret_cast<float4*>(out);
        int rsub = tid >> 6;
        int lane = tid & 63;
        for (int r = r0 + rsub; r < r1; r += 4) {
            if ((g_bm[r >> 5] >> (r & 31)) & 1u) continue;   // dest row: skip
            dst4[(size_t)r * 64 + lane] = src4[(size_t)r * 64 + lane];
        }
        return;
    }

    // ---------------- GEMM blocks ----------------
    const int warp = tid >> 5;
    const int lid  = tid & 31;

    const int w_base = blockIdx.x * WTILE;

    // stage window indices + dest slots (padded windows -> slot 0)
    #pragma unroll
    for (int rep = 0; rep < 4; rep++) {
        int t  = rep * 256 + tid;                      // 1024 entries
        int wl = t >> 5;
        int wg = w_base + wl;
        sm.widx[t] = (wg < W) ? widx[(size_t)wg * KWIN + (t & 31)] : 0;
    }
    if (tid < WTILE) {
        int wg = w_base + tid;
        sm.dst[tid] = (wg < W) ? dest[wg] : 0;
    }
    __syncthreads();

    // ---- cp.async stage issue: A 4 tasks/thread, B 1 task/thread ----
    auto issue_stage = [&](int it) {
        int b     = it & (NSTAGE - 1);
        int token = it >> 1;
        int half  = (it & 1) << 6;                     // 0 or 64 fp32
        uint32_t A_base = smem_u32(sm.A[b]);
        uint32_t B_base = smem_u32(sm.B[b]);
        #pragma unroll
        for (int rep = 0; rep < 4; rep++) {
            int t   = rep * 256 + tid;                 // 1024 tasks
            int row = t >> 4;                          // 0..63
            int c   = t & 15;                          // 16B chunk (4 fp32)
            int slot = sm.widx[(row >> 1) * KWIN + token];
            const float* src = buffer
                + ((size_t)slot * (NUM_HEADS * HEAD_DIM)
                   + (row & 1) * HEAD_DIM + half + c * 4);
            uint32_t dst = A_base + row * 256
                + ((uint32_t)((c * 2) ^ ((row & 7) << 2)) << 3);
            cp16(dst, src);
        }
        {
            int row = tid >> 3;                        // 0..31
            int ch  = tid & 7;                         // 16B chunk (8 bf16)
            const __nv_bfloat16* src = g_gw + (size_t)row * KD + it * KC + ch * 8;
            uint32_t dst = B_base + row * 128
                + ((uint32_t)(ch ^ (row & 7)) << 4);
            cp16(dst, src);
        }
        CP_COMMIT();
    };

    // ---- per-warp MMA geometry ----
    const int wm = (warp >> 1) * 16;                   // M rows wm..wm+15
    const int nb = (warp & 1) * 16;                    // N half
    const int gq = lid >> 3;
    const int rr = lid & 7;
    const int c2 = lid & 3;                            // k-pair index

    const int rowA0 = wm + (lid >> 2);
    const int rowA1 = rowA0 + 8;
    const uint32_t sA0 = (uint32_t)((rowA0 & 7) << 2);
    const uint32_t sA1 = (uint32_t)((rowA1 & 7) << 2);

    const int nB  = nb + ((gq >> 1) << 3) + rr;
    const int cB  = gq & 1;
    const uint32_t xB = (uint32_t)(nB & 7);

    float acc[2][4] = {};

    // ---- prologue: fill NSTAGE-1 stages ----
    #pragma unroll
    for (int s = 0; s < NSTAGE - 1; s++) issue_stage(s);

    // ---- mainloop ----
    for (int it = 0; it < NITER; it++) {
        int b = it & (NSTAGE - 1);
        CP_WAIT();
        __syncthreads();

        if (it + NSTAGE - 1 < NITER) issue_stage(it + NSTAGE - 1);
        else                         CP_COMMIT();      // keep group count uniform

        uint32_t Ab0 = smem_u32(sm.A[b]) + rowA0 * 256;
        uint32_t Ab1 = smem_u32(sm.A[b]) + rowA1 * 256;
        uint32_t Bb  = smem_u32(sm.B[b]) + nB * 128;

        #pragma unroll
        for (int q = 0; q < 4; q++) {                  // 4 k16 steps per chunk
            uint32_t g0 = (uint32_t)(q * 8 + c2);
            uint32_t g1 = g0 + 4;
            float2 f00 = lds64(Ab0 + ((g0 ^ sA0) << 3));
            float2 f01 = lds64(Ab1 + ((g0 ^ sA1) << 3));
            float2 f10 = lds64(Ab0 + ((g1 ^ sA0) << 3));
            float2 f11 = lds64(Ab1 + ((g1 ^ sA1) << 3));
            uint32_t a[4];
            a[0] = pack2(f00);
            a[1] = pack2(f01);
            a[2] = pack2(f10);
            a[3] = pack2(f11);
            uint32_t bf[4];
            uint32_t chB = ((uint32_t)(q * 2 + cB)) ^ xB;
            ldmatrix_x4(bf, Bb + (chB << 4));
            mma_bf16(acc[0], a, bf[0], bf[1]);
            mma_bf16(acc[1], a, bf[2], bf[3]);
        }
    }

    // ---- gates: sigmoid -> smem ----
    {
        int row0 = wm + (lid >> 2);
        int row1 = row0 + 8;
        #pragma unroll
        for (int j = 0; j < 2; j++) {
            int n0 = nb + j * 8 + (lid & 3) * 2;
            sm.g[row0 * NT + n0]     = sigf(acc[j][0]);
            sm.g[row0 * NT + n0 + 1] = sigf(acc[j][1]);
            sm.g[row1 * NT + n0]     = sigf(acc[j][2]);
            sm.g[row1 * NT + n0 + 1] = sigf(acc[j][3]);
        }
    }
    __syncthreads();

    // ---- gated reduction + scatter (tokens L2-hot) ----
    const int wsub = tid >> 6;
    const int h    = (tid >> 5) & 1;
    const int dq   = tid & 31;

    for (int p = 0; p < 8; p++) {
        int wl = p * 4 + wsub;
        int wg = w_base + wl;
        if (wg >= W) continue;
        const float* gp = sm.g + (wl * 2 + h) * NT;
        const int*   sp = sm.widx + wl * KWIN;
        float4 acc4 = make_float4(0.f, 0.f, 0.f, 0.f);
        #pragma unroll 8
        for (int k = 0; k < KWIN; k++) {
            float gk = gp[k];
            const float4 t4 = *reinterpret_cast<const float4*>(
                buffer + ((size_t)sp[k] * (NUM_HEADS * HEAD_DIM)
                          + h * HEAD_DIM + dq * 4));
            acc4.x += gk * t4.x;
            acc4.y += gk * t4.y;
            acc4.z += gk * t4.z;
            acc4.w += gk * t4.w;
        }
        *reinterpret_cast<float4*>(
            out + ((size_t)sm.dst[wl] * (NUM_HEADS * HEAD_DIM)
                   + h * HEAD_DIM + dq * 4)) = acc4;
    }
}

// ============================================================================
// Launch
// ============================================================================
extern "C" void kernel_launch(void* const* d_in, const int* in_sizes, int n_in,
                              void* d_out, int out_size)
{
    const float* buffer = (const float*)d_in[0];
    const float* cbuf   = (const float*)d_in[1];
    const float* gw     = (const float*)d_in[2];
    const int*   widx   = (const int*)d_in[3];
    const int*   dest   = (const int*)d_in[4];
    int W     = in_sizes[4];
    int crows = out_size / (NUM_HEADS * HEAD_DIM);

    cudaFuncSetAttribute(fused_kernel,
                         cudaFuncAttributeMaxDynamicSharedMemorySize, SMEM_BYTES);

    // gate_weight -> bf16 scratch
    cvt_gw_kernel<<<128, 256>>>(gw);
    // dest bitmap
    int nwords = (crows + 31) / 32;
    zero_bm_kernel<<<(nwords + 255) / 256, 256>>>(nwords);
    if (W > 0) set_bm_kernel<<<(W + 255) / 256, 256>>>(dest, W);

    int Mtot = 2 * W;
    int nblk = (Mtot + MT - 1) / MT;          // GEMM blocks (0 allowed)
    fused_kernel<<<nblk + NCOPY, 256, SMEM_BYTES>>>(
        buffer, cbuf, widx, dest, (float*)d_out, W, Mtot, nblk, crows);
}